// round 5
// baseline (speedup 1.0000x reference)
#include <cuda_runtime.h>

// OptimizerNetwork: 2-layer LSTM-cell meta-optimizer, N=1e6 rows, H=20.
// History: R1 383 (LDS-bound) -> R3 334 (const-bank split) -> R4 306
// (tanh.approx, 96 regs, 5 blk/SM). All pipes ~45-70%: latency-bound at 2x
// pipe floors. R5: register diet for 6 blocks/SM (24 warps): stream c-state
// from gmem per-jj, fold output dot into cell2 (no h1n array), roll jj loop.

typedef unsigned long long ull;

// Weights in constant memory (filled each launch by captured async D2D copies).
__constant__ __align__(16) ull        cWih1v[80];    // [80][2] floats as pairs
__constant__ __align__(16) ulonglong2 cWih2v[400];   // [80][5] f32x2-pair quads
__constant__ __align__(16) ull        cB1v[80];      // interleaved (bih1, bhh1)
__constant__ __align__(16) ull        cB2v[80];      // interleaved (bih2, bhh2)
__constant__ __align__(16) ull        cWoutv[10];    // [20] floats as pairs
__constant__ float cBoutv;

__device__ __forceinline__ ull pk(float a, float b) {
    ull r; asm("mov.b64 %0, {%1,%2};" : "=l"(r) : "f"(a), "f"(b)); return r;
}
__device__ __forceinline__ void upk(ull p, float& a, float& b) {
    asm("mov.b64 {%0,%1}, %2;" : "=f"(a), "=f"(b) : "l"(p));
}
__device__ __forceinline__ ull ffma2(ull a, ull b, ull c) {
    ull r; asm("fma.rn.f32x2 %0, %1, %2, %3;" : "=l"(r) : "l"(a), "l"(b), "l"(c)); return r;
}
__device__ __forceinline__ float hsum(ull p) { float a, b; upk(p, a, b); return a + b; }

__device__ __forceinline__ float tanha(float x) {
    float r; asm("tanh.approx.f32 %0, %1;" : "=f"(r) : "f"(x)); return r;
}
__device__ __forceinline__ float sigm(float x) {
    return fmaf(0.5f, tanha(0.5f * x), 0.5f);
}

// One LSTM cell, one row.
//  L==1: x = 1 packed pair; h-out written to hout[10] (kept for cell2).
//  L==2: x = 10 pairs; h-out streamed to gmem (hng) and folded into *accout.
// c-in streamed from gmem (cin_g, LDG.64/iter); c-out streamed to cout_g.
// Whh rows from shared; Wih + interleaved (bih,bhh) bias from constant bank
// (hsum folds both bias halves).
template <int L>
__device__ __forceinline__ void lstm_cell(
    const ull* __restrict__ xin, const float* __restrict__ sWhh,
    const ull* __restrict__ hin, ull* __restrict__ hout,
    const ull* __restrict__ cin_g, ull* __restrict__ cout_g,
    ull* __restrict__ hng, ull* __restrict__ accout)
{
#pragma unroll 1
    for (int jj = 0; jj < 10; ++jj) {
        ull cv = cin_g[jj];                    // LDG.64, hidden under gate math
        float gv[8];
#pragma unroll
        for (int u = 0; u < 2; ++u) {
            const int j = 2 * jj + u;
#pragma unroll
            for (int g = 0; g < 4; ++g) {
                const int r = g * 20 + j;
                ull acc = (L == 1) ? cB1v[r] : cB2v[r];   // (bih, bhh) packed
                if (L == 1) {
                    acc = ffma2(xin[0], cWih1v[r], acc);
                } else {
#pragma unroll
                    for (int k = 0; k < 5; ++k) {
                        ulonglong2 w = cWih2v[r * 5 + k];
                        acc = ffma2(xin[2 * k],     w.x, acc);
                        acc = ffma2(xin[2 * k + 1], w.y, acc);
                    }
                }
                const ulonglong2* wh = (const ulonglong2*)(sWhh + r * 20);
#pragma unroll
                for (int k = 0; k < 5; ++k) {
                    ulonglong2 w = wh[k];
                    acc = ffma2(hin[2 * k],     w.x, acc);
                    acc = ffma2(hin[2 * k + 1], w.y, acc);
                }
                gv[u * 4 + g] = hsum(acc);
            }
        }
        float i0 = sigm(gv[0]), f0 = sigm(gv[1]), g0 = tanha(gv[2]), o0 = sigm(gv[3]);
        float i1 = sigm(gv[4]), f1 = sigm(gv[5]), g1 = tanha(gv[6]), o1 = sigm(gv[7]);
        float ca, cb; upk(cv, ca, cb);
        float cn0 = fmaf(f0, ca, i0 * g0);
        float cn1 = fmaf(f1, cb, i1 * g1);
        cout_g[jj] = pk(cn0, cn1);
        ull hp = pk(o0 * tanha(cn0), o1 * tanha(cn1));
        if (L == 1) {
            hout[jj] = hp;
        } else {
            hng[jj] = hp;                               // STG.64 h1n
            *accout = ffma2(hp, cWoutv[jj], *accout);   // fold output dot
        }
    }
}

__global__ void __launch_bounds__(128, 6)
optnet_kernel(const float* __restrict__ inp,
              const float* __restrict__ h0, const float* __restrict__ h1,
              const float* __restrict__ c0, const float* __restrict__ c1,
              const float* __restrict__ Whh1g, const float* __restrict__ Whh2g,
              float* __restrict__ out, int N)
{
    __shared__ __align__(16) float sWhh1[1600];
    __shared__ __align__(16) float sWhh2[1600];
    const int tid = threadIdx.x, bd = blockDim.x;
    for (int i = tid; i < 400; i += bd) {
        ((float4*)sWhh1)[i] = ((const float4*)Whh1g)[i];
        ((float4*)sWhh2)[i] = ((const float4*)Whh2g)[i];
    }
    __syncthreads();

    const size_t row = (size_t)blockIdx.x * bd + tid;
    if (row >= (size_t)N) return;

    // ---- preprocess ----
    float x = inp[row];
    float ax = fabsf(x);
    float pa, pb;
    if (ax >= 4.5399930e-05f) {            // exp(-10)
        pa = __logf(ax + 1e-8f) * 0.1f;
        pb = (x > 0.f) ? 1.f : -1.f;
    } else {
        pa = -1.f;
        pb = 22026.4658f * x;              // exp(10)
    }
    ull xp[1]; xp[0] = pk(pa, pb);

    // tuple order: out, h0n, h1n, c0n, c1n
    float* h0n_out = out + (size_t)N;
    float* h1n_out = out + (size_t)N * 21;
    float* c0n_out = out + (size_t)N * 41;
    float* c1n_out = out + (size_t)N * 61;

    ull A[10], B[10];                      // A = h-in, B = h0n (cell1 out)

#pragma unroll
    for (int q = 0; q < 5; ++q) {
        ulonglong2 v = ((const ulonglong2*)(h0 + row * 20))[q];
        A[2*q] = v.x; A[2*q+1] = v.y;
    }

    // ---- LSTM cell 1: h0n -> B, c0 streamed in, c0n streamed out ----
    lstm_cell<1>(xp, sWhh1, A, B,
                 (const ull*)(c0 + row * 20), (ull*)(c0n_out + row * 20),
                 nullptr, nullptr);

    // store h0n; load h1 -> A
#pragma unroll
    for (int q = 0; q < 5; ++q) {
        ulonglong2 v; v.x = B[2*q]; v.y = B[2*q+1];
        ((ulonglong2*)(h0n_out + row * 20))[q] = v;
        ulonglong2 w = ((const ulonglong2*)(h1 + row * 20))[q];
        A[2*q] = w.x; A[2*q+1] = w.y;
    }

    // ---- LSTM cell 2: x = h0n (B), h = h1 (A); h1n + out folded inline ----
    ull acc = pk(cBoutv, 0.f);
    lstm_cell<2>(B, sWhh2, A, nullptr,
                 (const ull*)(c1 + row * 20), (ull*)(c1n_out + row * 20),
                 (ull*)(h1n_out + row * 20), &acc);

    out[row] = hsum(acc);
}

extern "C" void kernel_launch(void* const* d_in, const int* in_sizes, int n_in,
                              void* d_out, int out_size)
{
    const float* inp  = (const float*)d_in[0];
    const float* h0   = (const float*)d_in[1];
    const float* h1   = (const float*)d_in[2];
    const float* c0   = (const float*)d_in[3];
    const float* c1   = (const float*)d_in[4];
    // d_in[5]=Wih1 [80,2], [6]=Whh1, [7]=bih1, [8]=bhh1,
    // [9]=Wih2, [10]=Whh2, [11]=bih2, [12]=bhh2, [13]=Wout, [14]=bout

    // Stage small weights into the constant bank (async D2D; graph-capturable).
    cudaMemcpyToSymbolAsync(cWih1v, d_in[5], 160 * 4, 0,
                            cudaMemcpyDeviceToDevice, 0);
    cudaMemcpyToSymbolAsync(cWih2v, d_in[9], 1600 * 4, 0,
                            cudaMemcpyDeviceToDevice, 0);
    cudaMemcpyToSymbolAsync(cWoutv, d_in[13], 20 * 4, 0,
                            cudaMemcpyDeviceToDevice, 0);
    cudaMemcpyToSymbolAsync(cBoutv, d_in[14], 4, 0,
                            cudaMemcpyDeviceToDevice, 0);
    // Interleave biases: cB[r] = (bih[r], bhh[r]) via strided 2D copies.
    void* pB1 = nullptr; cudaGetSymbolAddress(&pB1, cB1v);
    void* pB2 = nullptr; cudaGetSymbolAddress(&pB2, cB2v);
    cudaMemcpy2DAsync(pB1, 8, d_in[7], 4, 4, 80, cudaMemcpyDeviceToDevice, 0);
    cudaMemcpy2DAsync((char*)pB1 + 4, 8, d_in[8], 4, 4, 80,
                      cudaMemcpyDeviceToDevice, 0);
    cudaMemcpy2DAsync(pB2, 8, d_in[11], 4, 4, 80, cudaMemcpyDeviceToDevice, 0);
    cudaMemcpy2DAsync((char*)pB2 + 4, 8, d_in[12], 4, 4, 80,
                      cudaMemcpyDeviceToDevice, 0);

    const int N = in_sizes[0];
    const int bd = 128;
    const int blocks = (N + bd - 1) / bd;
    optnet_kernel<<<blocks, bd>>>(inp, h0, h1, c0, c1,
                                  (const float*)d_in[6], (const float*)d_in[10],
                                  (float*)d_out, N);
}

// round 7
// speedup vs baseline: 2.0950x; 2.0950x over previous
#include <cuda_runtime.h>
#include <cuda_bf16.h>
#include <stdint.h>

// OptimizerNetwork: 2-layer LSTM-cell meta-optimizer, N=1e6 rows, H=20.
// R1-R5 scalar plateau ~306us (FMA/LDC/LDS all ~46%). R6 tcgen05 blocked:
// harness ptxas target sm_103 (no 'a') -> use base-PTX mma.sync (HMMA).
// Design: per-warp 32-row slab; gates = A[32,K] @ B[K,80] via m16n8k16 bf16,
// hi/lo split x3 passes (fp32-grade accuracy), fp32 accumulate.
//   - B rows gate-permuted so each thread's C frags hold full (i,f,g,o) quads
//     for its own (row,h) -> register-only epilogue, no smem transpose.
//   - bias folded in as a GEMM column (A col = 1.0, B col = bias).
//   - all staging warp-local: no __syncthreads in the main loop.
// Persistent grid, weights staged to smem once per CTA.

#define TPB 128
typedef unsigned uns;

// ---- smem layout (bytes) ----
#define A_OFF     0u        // [2][128][58] bf16; row stride 116B (29 words)
#define A_SPLIT   14848u
#define A_STRIDE  116u
#define B1_OFF    29696u    // [2][80][40] bf16; row stride 80B (20 words)
#define B1_SPLIT  6400u
#define B1_STRIDE 80u
#define B2_OFF    42496u    // [2][80][56] bf16; row stride 112B (28 words)
#define B2_SPLIT  8960u
#define B2_STRIDE 112u
#define WOUT_OFF  60416u    // float[20]
#define BOUT_OFF  60496u    // float
#define SMEM_BYTES 60512u

__device__ __forceinline__ float tanha(float x) {
    float r; asm("tanh.approx.f32 %0, %1;" : "=f"(r) : "f"(x)); return r;
}
__device__ __forceinline__ float sigm(float x) {
    return fmaf(0.5f, tanha(0.5f * x), 0.5f);
}

// store float pair as bf16 hi/lo into both A splits (cols col, col+1; col even)
__device__ __forceinline__ void stA2(char* sm, int row, int col, float a, float b) {
    __nv_bfloat16 ah = __float2bfloat16(a), bh = __float2bfloat16(b);
    __nv_bfloat162 hv; hv.x = ah; hv.y = bh;
    __nv_bfloat162 lv;
    lv.x = __float2bfloat16(a - __bfloat162float(ah));
    lv.y = __float2bfloat16(b - __bfloat162float(bh));
    char* p = sm + A_OFF + row * A_STRIDE + col * 2;
    *(__nv_bfloat162*)p = hv;
    *(__nv_bfloat162*)(p + A_SPLIT) = lv;
}
// single bf16 hi/lo store into A (any col)
__device__ __forceinline__ void stA1(char* sm, int row, int col, float a) {
    __nv_bfloat16 h = __float2bfloat16(a);
    char* p = sm + A_OFF + row * A_STRIDE + col * 2;
    *(__nv_bfloat16*)p = h;
    *(__nv_bfloat16*)(p + A_SPLIT) = __float2bfloat16(a - __bfloat162float(h));
}
// B staging: single value hi/lo
__device__ __forceinline__ void stB(char* sm, uns off, uns split, uns stride,
                                    int row, int col, float v) {
    __nv_bfloat16 h = __float2bfloat16(v);
    char* p = sm + off + row * stride + col * 2;
    *(__nv_bfloat16*)p = h;
    *(__nv_bfloat16*)(p + split) = __float2bfloat16(v - __bfloat162float(h));
}

__device__ __forceinline__ void mma16816(float* c, const uns* a, const uns* b) {
    asm volatile("mma.sync.aligned.m16n8k16.row.col.f32.bf16.bf16.f32 "
        "{%0,%1,%2,%3}, {%4,%5,%6,%7}, {%8,%9}, {%0,%1,%2,%3};"
        : "+f"(c[0]), "+f"(c[1]), "+f"(c[2]), "+f"(c[3])
        : "r"(a[0]), "r"(a[1]), "r"(a[2]), "r"(a[3]), "r"(b[0]), "r"(b[1]));
}

// A fragment for m16n8k16: rows mbase+(l/4), +8; k = kb+(l%4)*2, +8
__device__ __forceinline__ void ldA(uns* a, const char* abase, int mbase, int kb, int l) {
    const char* p = abase + (mbase + (l >> 2)) * A_STRIDE + (kb + (l & 3) * 2) * 2;
    a[0] = *(const uns*)p;
    a[1] = *(const uns*)(p + 8 * A_STRIDE);
    a[2] = *(const uns*)(p + 16);
    a[3] = *(const uns*)(p + 8 * A_STRIDE + 16);
}
__device__ __forceinline__ void ldB(uns* b, const char* bbase, uns stride,
                                    int nbase, int kb, int l) {
    const char* p = bbase + (nbase + (l >> 2)) * stride + (kb + (l & 3) * 2) * 2;
    b[0] = *(const uns*)p;
    b[1] = *(const uns*)(p + 16);
}

// one cell GEMM: C[10][2][4] += A[32,16K]*B: 3 split passes (AhBh, AhBl, AlBh)
template <int KS>
__device__ __forceinline__ void gemm(float C[10][2][4], const char* sm,
                                     uns boff, uns bsplit, uns bstride,
                                     int wrow, int l) {
#pragma unroll
    for (int n = 0; n < 10; ++n)
#pragma unroll
        for (int m = 0; m < 2; ++m)
#pragma unroll
            for (int q = 0; q < 4; ++q) C[n][m][q] = 0.f;
#pragma unroll 1
    for (int sp = 0; sp < 3; ++sp) {
        const char* abase = sm + A_OFF + ((sp == 2) ? A_SPLIT : 0u);
        const char* bbase = sm + boff + ((sp == 1) ? bsplit : 0u);
#pragma unroll
        for (int k = 0; k < KS; ++k) {
            uns a0[4], a1[4];
            ldA(a0, abase, wrow, k * 16, l);
            ldA(a1, abase, wrow + 16, k * 16, l);
#pragma unroll
            for (int n = 0; n < 10; ++n) {
                uns b[2];
                ldB(b, bbase, bstride, n * 8, k * 16, l);
                mma16816(C[n][0], a0, b);
                mma16816(C[n][1], a1, b);
            }
        }
    }
}

__global__ void __launch_bounds__(TPB, 3)
optnet_mma(const float* __restrict__ inp,
           const float* __restrict__ h0g, const float* __restrict__ h1g,
           const float* __restrict__ c0g, const float* __restrict__ c1g,
           const float* __restrict__ Wih1, const float* __restrict__ Whh1,
           const float* __restrict__ bih1, const float* __restrict__ bhh1,
           const float* __restrict__ Wih2, const float* __restrict__ Whh2,
           const float* __restrict__ bih2, const float* __restrict__ bhh2,
           const float* __restrict__ Wout, const float* __restrict__ bout,
           float* __restrict__ out, int N)
{
    extern __shared__ char sm[];
    const int tid = threadIdx.x;
    const int wid = tid >> 5;
    const int l = tid & 31;

    // ---- prologue: stage permuted weight tiles (hi/lo) + bias columns ----
    // B row p: p=2h -> i_h (W row h), p=2h+1 -> f_h (20+h),
    //          p=40+2h -> g_h (40+h), p=41+2h -> o_h (60+h)
    if (tid < 80) {
        const int p = tid;
        int h, r;
        if (p < 40) { h = p >> 1; r = (p & 1) ? 20 + h : h; }
        else { int q = p - 40; h = q >> 1; r = (q & 1) ? 60 + h : 40 + h; }
        // cell1: cols 0,1 = Wih1; 2..21 = Whh1; 22 = bias; 23..39 = 0
        stB(sm, B1_OFF, B1_SPLIT, B1_STRIDE, p, 0, Wih1[r * 2 + 0]);
        stB(sm, B1_OFF, B1_SPLIT, B1_STRIDE, p, 1, Wih1[r * 2 + 1]);
        for (int k = 0; k < 20; ++k)
            stB(sm, B1_OFF, B1_SPLIT, B1_STRIDE, p, 2 + k, Whh1[r * 20 + k]);
        stB(sm, B1_OFF, B1_SPLIT, B1_STRIDE, p, 22, bih1[r] + bhh1[r]);
        for (int c = 23; c < 40; ++c)
            stB(sm, B1_OFF, B1_SPLIT, B1_STRIDE, p, c, 0.f);
        // cell2: cols 0..19 = Wih2; 20..39 = Whh2; 40 = bias; 41..55 = 0
        for (int k = 0; k < 20; ++k)
            stB(sm, B2_OFF, B2_SPLIT, B2_STRIDE, p, k, Wih2[r * 20 + k]);
        for (int k = 0; k < 20; ++k)
            stB(sm, B2_OFF, B2_SPLIT, B2_STRIDE, p, 20 + k, Whh2[r * 20 + k]);
        stB(sm, B2_OFF, B2_SPLIT, B2_STRIDE, p, 40, bih2[r] + bhh2[r]);
        for (int c = 41; c < 56; ++c)
            stB(sm, B2_OFF, B2_SPLIT, B2_STRIDE, p, c, 0.f);
    }
    if (tid < 20) ((float*)(sm + WOUT_OFF))[tid] = Wout[tid];
    if (tid == 0) *(float*)(sm + BOUT_OFF) = bout[0];
    __syncthreads();

    // per-thread loop-invariant Wout values (h = l%4 + 4j)
    float woutR[5];
#pragma unroll
    for (int j = 0; j < 5; ++j)
        woutR[j] = ((const float*)(sm + WOUT_OFF))[(l & 3) + 4 * j];
    const float boutv = *(const float*)(sm + BOUT_OFF);

    // output tuple sections: out, h0n@N, h1n@21N, c0n@41N, c1n@61N
    float* h0n_out = out + (size_t)N;
    float* h1n_out = out + (size_t)N * 21;
    float* c0n_out = out + (size_t)N * 41;
    float* c1n_out = out + (size_t)N * 61;

    const int wrow = wid * 32;                 // warp's local A row base
    const int nslabs = (N + 31) / 32;
    const int twarps = gridDim.x * 4;
    float C[10][2][4];

    for (int s = blockIdx.x * 4 + wid; s < nslabs; s += twarps) {
        const int rowbase = s * 32;

        // ---- stage A cell1: x_pre (cols 0,1), h0 (2..21), bias 1.0 (22), 0s ----
        {
            const int grow = rowbase + l;
            float x = (grow < N) ? inp[grow] : 0.f;
            float ax = fabsf(x), pa, pb;
            if (ax >= 4.5399930e-05f) {        // exp(-10)
                pa = __logf(ax + 1e-8f) * 0.1f;
                pb = (x > 0.f) ? 1.f : -1.f;
            } else {
                pa = -1.f;
                pb = 22026.4658f * x;          // exp(10)
            }
            stA2(sm, wrow + l, 0, pa, pb);
            stA2(sm, wrow + l, 22, 1.f, 0.f);  // bias column
            stA2(sm, wrow + l, 24, 0.f, 0.f);
            stA2(sm, wrow + l, 26, 0.f, 0.f);
            stA2(sm, wrow + l, 28, 0.f, 0.f);
            stA2(sm, wrow + l, 30, 0.f, 0.f);
            // h0: coalesced float4 rounds
#pragma unroll
            for (int q = 0; q < 5; ++q) {
                const int idx = q * 32 + l;          // float4 id in slab
                const int gr = idx / 5, cp = idx % 5;
                float4 v = make_float4(0.f, 0.f, 0.f, 0.f);
                if (rowbase + gr < N)
                    v = ((const float4*)(h0g + (size_t)rowbase * 20))[idx];
                stA2(sm, wrow + gr, 2 + cp * 4, v.x, v.y);
                stA2(sm, wrow + gr, 4 + cp * 4, v.z, v.w);
            }
        }
        __syncwarp();

        // ---- cell1 GEMM: K=32 (2 k-steps) ----
        gemm<2>(C, sm, B1_OFF, B1_SPLIT, B1_STRIDE, wrow, l);
        __syncwarp();

        // ---- epilogue 1 + stage A cell2 ----
        // thread owns rows (l/4 + 8*rs), h = (l%4)+4j; quad: (i,f)=C[j], (g,o)=C[j+5]
#pragma unroll
        for (int rs = 0; rs < 4; ++rs) {
            const int mt = rs >> 1, cb = (rs & 1) * 2;
            const int rloc = (l >> 2) + 8 * rs;
            const size_t grow = (size_t)rowbase + rloc;
            const bool ok = grow < (size_t)N;
#pragma unroll
            for (int j = 0; j < 5; ++j) {
                const int h = (l & 3) + 4 * j;
                float I = sigm(C[j][mt][cb]);
                float F = sigm(C[j][mt][cb + 1]);
                float G = tanha(C[j + 5][mt][cb]);
                float O = sigm(C[j + 5][mt][cb + 1]);
                float cin = ok ? c0g[grow * 20 + h] : 0.f;
                float cn = fmaf(F, cin, I * G);
                float hn = O * tanha(cn);
                if (ok) {
                    c0n_out[grow * 20 + h] = cn;
                    h0n_out[grow * 20 + h] = hn;
                }
                stA1(sm, wrow + rloc, h, hn);     // cell2 A cols 0..19
            }
        }
        // stage h1 (cols 20..39) + bias col 40 + zeros
        {
            stA2(sm, wrow + l, 40, 1.f, 0.f);
            stA2(sm, wrow + l, 42, 0.f, 0.f);
            stA2(sm, wrow + l, 44, 0.f, 0.f);
            stA2(sm, wrow + l, 46, 0.f, 0.f);
#pragma unroll
            for (int q = 0; q < 5; ++q) {
                const int idx = q * 32 + l;
                const int gr = idx / 5, cp = idx % 5;
                float4 v = make_float4(0.f, 0.f, 0.f, 0.f);
                if (rowbase + gr < N)
                    v = ((const float4*)(h1g + (size_t)rowbase * 20))[idx];
                stA2(sm, wrow + gr, 20 + cp * 4, v.x, v.y);
                stA2(sm, wrow + gr, 22 + cp * 4, v.z, v.w);
            }
        }
        __syncwarp();

        // ---- cell2 GEMM: K=48 (3 k-steps) ----
        gemm<3>(C, sm, B2_OFF, B2_SPLIT, B2_STRIDE, wrow, l);

        // ---- epilogue 2: c1n, h1n, out = h1n.Wout + bout ----
#pragma unroll
        for (int rs = 0; rs < 4; ++rs) {
            const int mt = rs >> 1, cb = (rs & 1) * 2;
            const int rloc = (l >> 2) + 8 * rs;
            const size_t grow = (size_t)rowbase + rloc;
            const bool ok = grow < (size_t)N;
            float psum = 0.f;
#pragma unroll
            for (int j = 0; j < 5; ++j) {
                const int h = (l & 3) + 4 * j;
                float I = sigm(C[j][mt][cb]);
                float F = sigm(C[j][mt][cb + 1]);
                float G = tanha(C[j + 5][mt][cb]);
                float O = sigm(C[j + 5][mt][cb + 1]);
                float cin = ok ? c1g[grow * 20 + h] : 0.f;
                float cn = fmaf(F, cin, I * G);
                float hn = O * tanha(cn);
                if (ok) {
                    c1n_out[grow * 20 + h] = cn;
                    h1n_out[grow * 20 + h] = hn;
                }
                psum = fmaf(hn, woutR[j], psum);
            }
            // reduce across the 4 lanes sharing this row (l%4 = 0..3)
            psum += __shfl_xor_sync(0xFFFFFFFFu, psum, 1);
            psum += __shfl_xor_sync(0xFFFFFFFFu, psum, 2);
            if (ok && (l & 3) == 0) out[grow] = psum + boutv;
        }
        __syncwarp();   // before next iteration restages A
    }
}

extern "C" void kernel_launch(void* const* d_in, const int* in_sizes, int n_in,
                              void* d_out, int out_size)
{
    static int configured = 0;
    if (!configured) {
        cudaFuncSetAttribute(optnet_mma,
                             cudaFuncAttributeMaxDynamicSharedMemorySize,
                             SMEM_BYTES);
        configured = 1;
    }
    const int N = in_sizes[0];
    const int grid = 444;   // 3 CTAs/SM x 148 SMs, persistent
    optnet_mma<<<grid, TPB, SMEM_BYTES>>>(
        (const float*)d_in[0], (const float*)d_in[1], (const float*)d_in[2],
        (const float*)d_in[3], (const float*)d_in[4],
        (const float*)d_in[5], (const float*)d_in[6],
        (const float*)d_in[7], (const float*)d_in[8],
        (const float*)d_in[9], (const float*)d_in[10],
        (const float*)d_in[11], (const float*)d_in[12],
        (const float*)d_in[13], (const float*)d_in[14],
        (float*)d_out, N);
}